// round 8
// baseline (speedup 1.0000x reference)
#include <cuda_runtime.h>
#include <cuda_bf16.h>
#include <math.h>
#include <stdint.h>

#define D     128
#define NMAX  50000
#define EMAX  800000
#define NPAD  (NMAX + 128)

// ---- scratch (device globals; zero-init; 16B-aligned) ----
__device__ __align__(16) float    g_T[NPAD * D];        // GEMM out * dinv
__device__ __align__(16) uint32_t g_Xh[NPAD * 64];      // split input (hi pairs), also A-split
__device__ __align__(16) uint32_t g_Xl[NPAD * 64];      // split input (lo pairs)
__device__ __align__(16) uint32_t g_Whi[2 * 8192];      // packed W hi pairs, [m][n][kp]
__device__ __align__(16) uint32_t g_Wlo[2 * 8192];
__device__ __align__(16) int   g_deg[NPAD];
__device__ int   g_rowptr[NMAX];
__device__ int   g_pos[NMAX];
__device__ int   g_eidx[EMAX];
__device__ float g_dinv[NMAX];
__device__ __align__(16) float g_gate[D];
__device__ __align__(16) float g_hbias[D];

// ---------------------------------------------------------------- bf16 split (fast)
// hi = rn(a,b) packed (a in low half); lo = rn(a-hi_a, b-hi_b) packed.
__device__ __forceinline__ void split2f(float a, float b, uint32_t& hi, uint32_t& lo) {
    asm("cvt.rn.bf16x2.f32 %0, %1, %2;" : "=r"(hi) : "f"(b), "f"(a));
    float ha = __uint_as_float(hi << 16);
    float hb = __uint_as_float(hi & 0xffff0000u);
    float la = a - ha;
    float lb = b - hb;
    asm("cvt.rn.bf16x2.f32 %0, %1, %2;" : "=r"(lo) : "f"(lb), "f"(la));
}

// ---------------------------------------------------------------- degrees
__global__ void k_deg_init(int n) {
    int i = blockIdx.x * blockDim.x + threadIdx.x;
    if (i < n) g_deg[i] = 1;
}

// vectorized: 4 edges/thread (requires E%4==0 and 16B-aligned edst)
__global__ void k_deg_count4(const int4* __restrict__ edst4, int E4, int n) {
    int i = blockIdx.x * blockDim.x + threadIdx.x;
    if (i >= E4) return;
    int4 d = edst4[i];
    if ((unsigned)d.x < (unsigned)n) atomicAdd(&g_deg[d.x], 1);
    if ((unsigned)d.y < (unsigned)n) atomicAdd(&g_deg[d.y], 1);
    if ((unsigned)d.z < (unsigned)n) atomicAdd(&g_deg[d.z], 1);
    if ((unsigned)d.w < (unsigned)n) atomicAdd(&g_deg[d.w], 1);
}
__global__ void k_deg_count1(const int* __restrict__ edst, int E, int n) {
    int i = blockIdx.x * blockDim.x + threadIdx.x;
    if (i < E) {
        int d = edst[i];
        if ((unsigned)d < (unsigned)n) atomicAdd(&g_deg[d], 1);
    }
}

// ---------------------------------------------------------------- scan (rowptr, cursors, dinv)
__global__ void k_scan(int n) {
    __shared__ int part[1024];
    int tid = threadIdx.x;
    const int per = 52;                    // 1024*52 >= 50000, multiple of 4
    int base = tid * per;
    int s = 0;
    for (int i = 0; i < per; i += 4) {
        int r = base + i;
        if (r + 3 < n) {
            int4 v = *((const int4*)&g_deg[r]);
            s += v.x + v.y + v.z + v.w - 4;
        } else {
#pragma unroll
            for (int u = 0; u < 4; u++) {
                int rr = r + u;
                if (rr < n) s += g_deg[rr] - 1;
            }
        }
    }
    part[tid] = s;
    __syncthreads();
    for (int off = 1; off < 1024; off <<= 1) {
        int v = (tid >= off) ? part[tid - off] : 0;
        __syncthreads();
        part[tid] += v;
        __syncthreads();
    }
    int run = (tid == 0) ? 0 : part[tid - 1];
    for (int i = 0; i < per; i += 4) {
        int r = base + i;
        if (r >= n) break;
        int4 v;
        if (r + 3 < n) v = *((const int4*)&g_deg[r]);
        else {
            v.x = (r     < n) ? g_deg[r]     : 1;
            v.y = (r + 1 < n) ? g_deg[r + 1] : 1;
            v.z = (r + 2 < n) ? g_deg[r + 2] : 1;
            v.w = (r + 3 < n) ? g_deg[r + 3] : 1;
        }
        int dv[4] = {v.x, v.y, v.z, v.w};
#pragma unroll
        for (int u = 0; u < 4; u++) {
            int rr = r + u;
            if (rr < n) {
                g_rowptr[rr] = run;
                g_pos[rr]    = run;
                run += dv[u] - 1;
                g_dinv[rr] = rsqrtf((float)dv[u]);
            }
        }
    }
}

// ---------------------------------------------------------------- CSR fill
__global__ void k_csr_fill4(const int4* __restrict__ esrc4,
                            const int4* __restrict__ edst4, int E4, int n) {
    int i = blockIdx.x * blockDim.x + threadIdx.x;
    if (i >= E4) return;
    int4 s = esrc4[i];
    int4 d = edst4[i];
    if ((unsigned)s.x < (unsigned)n && (unsigned)d.x < (unsigned)n) {
        int p = atomicAdd(&g_pos[d.x], 1); if (p < EMAX) g_eidx[p] = s.x;
    }
    if ((unsigned)s.y < (unsigned)n && (unsigned)d.y < (unsigned)n) {
        int p = atomicAdd(&g_pos[d.y], 1); if (p < EMAX) g_eidx[p] = s.y;
    }
    if ((unsigned)s.z < (unsigned)n && (unsigned)d.z < (unsigned)n) {
        int p = atomicAdd(&g_pos[d.z], 1); if (p < EMAX) g_eidx[p] = s.z;
    }
    if ((unsigned)s.w < (unsigned)n && (unsigned)d.w < (unsigned)n) {
        int p = atomicAdd(&g_pos[d.w], 1); if (p < EMAX) g_eidx[p] = s.w;
    }
}
__global__ void k_csr_fill1(const int* __restrict__ esrc,
                            const int* __restrict__ edst, int E, int n) {
    int i = blockIdx.x * blockDim.x + threadIdx.x;
    if (i >= E) return;
    int s = esrc[i];
    int d = edst[i];
    if ((unsigned)s >= (unsigned)n || (unsigned)d >= (unsigned)n) return;
    int slot = atomicAdd(&g_pos[d], 1);
    if (slot < EMAX) g_eidx[slot] = s;
}

// ---------------------------------------------------------------- constants: W split/pack + hypernet (fused)
// blocks 0..63: W prep (16384 elements). blocks 64..79: gate/bias (128 warps).
__global__ void k_const(const float* __restrict__ W1, const float* __restrict__ W2,
                        const float* __restrict__ ctx, const float* __restrict__ Wg,
                        const float* __restrict__ bg, const float* __restrict__ Wb) {
    int blk = blockIdx.x;
    if (blk < 64) {
        int idx = blk * 256 + threadIdx.x;              // 0..16383
        int m  = idx >> 13;
        int r  = idx & 8191;
        int nn = r & 127;
        int kp = r >> 7;                                // 0..63
        const float* W = m ? W2 : W1;
        float w0 = W[(2 * kp) * D + nn];
        float w1 = W[(2 * kp + 1) * D + nn];
        uint32_t hi, lo;
        split2f(w0, w1, hi, lo);
        g_Whi[m * 8192 + nn * 64 + kp] = hi;
        g_Wlo[m * 8192 + nn * 64 + kp] = lo;
    } else {
        int w    = (blk - 64) * 8 + (threadIdx.x >> 5); // column 0..127
        int lane = threadIdx.x & 31;
        float c0 = ctx[lane], c1 = ctx[lane + 32];
        float g = c0 * Wg[lane * D + w] + c1 * Wg[(lane + 32) * D + w];
        float b = c0 * Wb[lane * D + w] + c1 * Wb[(lane + 32) * D + w];
#pragma unroll
        for (int o = 16; o > 0; o >>= 1) {
            g += __shfl_down_sync(0xffffffffu, g, o);
            b += __shfl_down_sync(0xffffffffu, b, o);
        }
        if (lane == 0) {
            g_gate[w]  = 1.f / (1.f + __expf(-(g + bg[w])));
            g_hbias[w] = b;
        }
    }
}

// ---------------------------------------------------------------- input split: x -> (g_Xh, g_Xl)
__global__ void k_split(const float* __restrict__ X, int n) {
    int i = blockIdx.x * blockDim.x + threadIdx.x;      // float4 index
    if (i >= n * 32) return;
    float4 v = ((const float4*)X)[i];
    int row = i >> 5, c4 = i & 31;
    uint32_t h01, l01, h23, l23;
    split2f(v.x, v.y, h01, l01);
    split2f(v.z, v.w, h23, l23);
    *((uint2*)&g_Xh[(size_t)row * 64 + c4 * 2]) = make_uint2(h01, h23);
    *((uint2*)&g_Xl[(size_t)row * 64 + c4 * 2]) = make_uint2(l01, l23);
}

// ---------------------------------------------------------------- bf16x3 tensor-core GEMM (pre-split inputs)
// T[r][:] = (X[r][:] @ W) * dinv[r];  D = Xhi@Whi + Xhi@Wlo + Xlo@Whi
#define PS 68      // padded row stride (words)

__device__ __forceinline__ void mma16816(float* c, uint32_t a0, uint32_t a1,
                                         uint32_t a2, uint32_t a3,
                                         uint32_t b0, uint32_t b1) {
    asm volatile("mma.sync.aligned.m16n8k16.row.col.f32.bf16.bf16.f32 "
                 "{%0,%1,%2,%3}, {%4,%5,%6,%7}, {%8,%9}, {%0,%1,%2,%3};"
                 : "+f"(c[0]), "+f"(c[1]), "+f"(c[2]), "+f"(c[3])
                 : "r"(a0), "r"(a1), "r"(a2), "r"(a3), "r"(b0), "r"(b1));
}

__global__ void __launch_bounds__(256)
k_gemm(int wsel, float* __restrict__ T, int n) {
    extern __shared__ uint32_t sm[];
    uint32_t* Xh = sm;                  // 128*PS
    uint32_t* Xl = Xh + 128 * PS;
    uint32_t* Wh = Xl + 128 * PS;
    uint32_t* Wl = Wh + 128 * PS;
    int tid = threadIdx.x;
    int r0  = blockIdx.x * 128;

    // copy packed W (8192 words = 2048 uint4 each)
    const uint32_t* gwh = g_Whi + wsel * 8192;
    const uint32_t* gwl = g_Wlo + wsel * 8192;
#pragma unroll
    for (int i = 0; i < 8; i++) {
        int q  = tid + i * 256;
        int wb = q * 4;
        int nn = wb >> 6, kp = wb & 63;
        *((uint4*)&Wh[nn * PS + kp]) = ((const uint4*)gwh)[q];
        *((uint4*)&Wl[nn * PS + kp]) = ((const uint4*)gwl)[q];
    }
    // copy pre-split X tile (rows r0..r0+127; 16 uint4 per row)
    const uint4* gxh = (const uint4*)g_Xh + (size_t)r0 * 16;
    const uint4* gxl = (const uint4*)g_Xl + (size_t)r0 * 16;
#pragma unroll
    for (int i = 0; i < 8; i++) {
        int q   = tid + i * 256;        // 0..2047
        int row = q >> 4, k4 = q & 15;
        *((uint4*)&Xh[row * PS + k4 * 4]) = gxh[q];
        *((uint4*)&Xl[row * PS + k4 * 4]) = gxl[q];
    }
    __syncthreads();

    int wid  = tid >> 5;
    int lane = tid & 31;
    int g    = lane >> 2;
    int tig  = lane & 3;
    int rA   = wid * 16 + g;

    float acc[16][4];
#pragma unroll
    for (int t = 0; t < 16; t++)
#pragma unroll
        for (int c = 0; c < 4; c++) acc[t][c] = 0.f;

#pragma unroll
    for (int s = 0; s < 8; s++) {
        int kp = s * 8;
        uint32_t ah0 = Xh[rA * PS + kp + tig];
        uint32_t ah1 = Xh[(rA + 8) * PS + kp + tig];
        uint32_t ah2 = Xh[rA * PS + kp + tig + 4];
        uint32_t ah3 = Xh[(rA + 8) * PS + kp + tig + 4];
        uint32_t al0 = Xl[rA * PS + kp + tig];
        uint32_t al1 = Xl[(rA + 8) * PS + kp + tig];
        uint32_t al2 = Xl[rA * PS + kp + tig + 4];
        uint32_t al3 = Xl[(rA + 8) * PS + kp + tig + 4];
#pragma unroll
        for (int nt = 0; nt < 16; nt++) {
            int nb = nt * 8 + g;
            uint32_t bh0 = Wh[nb * PS + kp + tig];
            uint32_t bh1 = Wh[nb * PS + kp + tig + 4];
            uint32_t bl0 = Wl[nb * PS + kp + tig];
            uint32_t bl1 = Wl[nb * PS + kp + tig + 4];
            mma16816(acc[nt], ah0, ah1, ah2, ah3, bh0, bh1);
            mma16816(acc[nt], ah0, ah1, ah2, ah3, bl0, bl1);
            mma16816(acc[nt], al0, al1, al2, al3, bh0, bh1);
        }
    }

    int gr0 = r0 + wid * 16 + g;
    int gr1 = gr0 + 8;
    float d0 = (gr0 < n) ? g_dinv[gr0] : 0.f;
    float d1 = (gr1 < n) ? g_dinv[gr1] : 0.f;
#pragma unroll
    for (int nt = 0; nt < 16; nt++) {
        int c = nt * 8 + 2 * tig;
        if (gr0 < n) {
            float2 o = make_float2(acc[nt][0] * d0, acc[nt][1] * d0);
            *((float2*)&T[(size_t)gr0 * D + c]) = o;
        }
        if (gr1 < n) {
            float2 o = make_float2(acc[nt][2] * d1, acc[nt][3] * d1);
            *((float2*)&T[(size_t)gr1 * D + c]) = o;
        }
    }
}

// ---------------------------------------------------------------- fused CSR gather + epilogue
// MODE 1: leaky_relu -> writes split-bf16 into g_Xh/g_Xl (GEMM2 input)
// MODE 2: *gate + hbias -> writes fp32 Out
template <int MODE>
__global__ void k_gather(const float* __restrict__ T,
                         float* __restrict__ Out,
                         const float* __restrict__ bvec, int n) {
    int w = (blockIdx.x * blockDim.x + threadIdx.x) >> 5;
    if (w >= n) return;
    int lane = threadIdx.x & 31;
    int beg = g_rowptr[w];
    int cnt = g_deg[w] - 1;

    float4 acc[8];
    acc[0] = ((const float4*)(T + (size_t)w * D))[lane];   // self term
#pragma unroll
    for (int u = 1; u < 8; u++) acc[u] = make_float4(0.f, 0.f, 0.f, 0.f);

    int j = 0;
    while (j < cnt) {
        int chunk = min(cnt - j, 32);
        int myidx = (lane < chunk) ? g_eidx[beg + j + lane] : 0;
        int t = 0;
        for (; t + 7 < chunk; t += 8) {
#pragma unroll
            for (int u = 0; u < 8; u++) {
                int s = __shfl_sync(0xffffffffu, myidx, t + u);
                float4 v = ((const float4*)(T + (size_t)s * D))[lane];
                acc[u].x += v.x; acc[u].y += v.y; acc[u].z += v.z; acc[u].w += v.w;
            }
        }
        for (; t < chunk; t++) {
            int s = __shfl_sync(0xffffffffu, myidx, t);
            float4 v = ((const float4*)(T + (size_t)s * D))[lane];
            acc[0].x += v.x; acc[0].y += v.y; acc[0].z += v.z; acc[0].w += v.w;
        }
        j += chunk;
    }
#pragma unroll
    for (int u = 1; u < 8; u++) {
        acc[0].x += acc[u].x; acc[0].y += acc[u].y;
        acc[0].z += acc[u].z; acc[0].w += acc[u].w;
    }

    float di = g_dinv[w];
    float4 b = ((const float4*)bvec)[lane];
    float4 o;
    o.x = acc[0].x * di + b.x;
    o.y = acc[0].y * di + b.y;
    o.z = acc[0].z * di + b.z;
    o.w = acc[0].w * di + b.w;
    if (MODE == 1) {
        o.x = o.x > 0.f ? o.x : 0.2f * o.x;
        o.y = o.y > 0.f ? o.y : 0.2f * o.y;
        o.z = o.z > 0.f ? o.z : 0.2f * o.z;
        o.w = o.w > 0.f ? o.w : 0.2f * o.w;
        uint32_t h01, l01, h23, l23;
        split2f(o.x, o.y, h01, l01);
        split2f(o.z, o.w, h23, l23);
        *((uint2*)&g_Xh[(size_t)w * 64 + lane * 2]) = make_uint2(h01, h23);
        *((uint2*)&g_Xl[(size_t)w * 64 + lane * 2]) = make_uint2(l01, l23);
    } else {
        float4 gt = ((const float4*)g_gate)[lane];
        float4 hb = ((const float4*)g_hbias)[lane];
        o.x = o.x * gt.x + hb.x;
        o.y = o.y * gt.y + hb.y;
        o.z = o.z * gt.z + hb.z;
        o.w = o.w * gt.w + hb.w;
        ((float4*)(Out + (size_t)w * D))[lane] = o;
    }
}

// ----------------------------------------------------------------
extern "C" void kernel_launch(void* const* d_in, const int* in_sizes, int n_in,
                              void* d_out, int out_size) {
    const float* x    = (const float*)d_in[0];
    const float* ctx  = (const float*)d_in[1];
    const float* W1   = (const float*)d_in[2];
    const float* b1   = (const float*)d_in[3];
    const float* W2   = (const float*)d_in[4];
    const float* b2   = (const float*)d_in[5];
    const float* Wg   = (const float*)d_in[6];
    const float* bg   = (const float*)d_in[7];
    const float* Wb   = (const float*)d_in[8];
    const int*   ei   = (const int*)d_in[9];     // int32 (JAX x64 disabled)
    float*       out  = (float*)d_out;

    int N = in_sizes[0] / D;
    int E = in_sizes[9] / 2;
    const int* esrc = ei;
    const int* edst = ei + E;

    float* pT;
    cudaGetSymbolAddress((void**)&pT, g_T);

    int smemG = 4 * 128 * PS * sizeof(uint32_t);          // 139264 B
    cudaFuncSetAttribute(k_gemm,
                         cudaFuncAttributeMaxDynamicSharedMemorySize, smemG);

    int nbN  = (N + 255) / 256;
    int gblk = (N + 127) / 128;
    long long gth = (long long)N * 32;
    int nbG  = (int)((gth + 255) / 256);
    int nbS  = (N * 32 + 255) / 256;

    bool vec = (E % 4 == 0) &&
               ((((uintptr_t)esrc) & 15) == 0) && ((((uintptr_t)edst) & 15) == 0);

    // degree + CSR build
    k_deg_init<<<nbN, 256>>>(N);
    if (vec) {
        int E4 = E / 4;
        int nb4 = (E4 + 255) / 256;
        k_deg_count4<<<nb4, 256>>>((const int4*)edst, E4, N);
        k_scan<<<1, 1024>>>(N);
        k_csr_fill4<<<nb4, 256>>>((const int4*)esrc, (const int4*)edst, E4, N);
    } else {
        int nbE = (E + 255) / 256;
        k_deg_count1<<<nbE, 256>>>(edst, E, N);
        k_scan<<<1, 1024>>>(N);
        k_csr_fill1<<<nbE, 256>>>(esrc, edst, E, N);
    }

    // constants (W split + hypernet) and input split
    k_const<<<80, 256>>>(W1, W2, ctx, Wg, bg, Wb);
    k_split<<<nbS, 256>>>(x, N);

    // conv1: A = leaky( dinv .* (T_self + gather) + b1 )  [A emitted pre-split]
    k_gemm<<<gblk, 256, smemG>>>(0, pT, N);
    k_gather<1><<<nbG, 256>>>(pT, nullptr, b1, N);

    // conv2: out = ( dinv .* (T_self + gather) + b2 ) * gate + hbias
    k_gemm<<<gblk, 256, smemG>>>(1, pT, N);
    k_gather<2><<<nbG, 256>>>(pT, out, b2, N);
}